// round 1
// baseline (speedup 1.0000x reference)
#include <cuda_runtime.h>

// Analytical collapse of the 4-wire / 4-layer RY–RZ–CNOT circuit:
//   * RZ phases are diagonal & unit-modulus -> probabilities unaffected.
//   * The CNOT chain is the GF(2) map T (lower-triangular ones); T^4 = I,
//     so after 4 layers the basis permutation is the identity.
//   * State stays a product state in probability: <Z_w> = cos(x_w).
// => out[b][w] = cos(x[b][w]); weights unused. Pure HBM-bound elementwise op.

__global__ void qk_cos_kernel(const float4* __restrict__ x, float4* __restrict__ out, int n4) {
    int i = blockIdx.x * blockDim.x + threadIdx.x;
    if (i < n4) {
        float4 v = x[i];
        float4 r;
        r.x = cosf(v.x);
        r.y = cosf(v.y);
        r.z = cosf(v.z);
        r.w = cosf(v.w);
        out[i] = r;
    }
}

// Tail handler for element counts not divisible by 4 (not expected here, but safe).
__global__ void qk_cos_tail(const float* __restrict__ x, float* __restrict__ out,
                            int start, int n) {
    int i = start + blockIdx.x * blockDim.x + threadIdx.x;
    if (i < n) out[i] = cosf(x[i]);
}

extern "C" void kernel_launch(void* const* d_in, const int* in_sizes, int n_in,
                              void* d_out, int out_size) {
    const float* x = (const float*)d_in[0];   // (BATCH, 4) float32
    float* out = (float*)d_out;               // (BATCH, 4) float32
    int n = out_size;                          // 1048576
    int n4 = n >> 2;

    const int T = 256;
    int blocks = (n4 + T - 1) / T;
    qk_cos_kernel<<<blocks, T>>>((const float4*)x, (float4*)out, n4);

    int rem = n - (n4 << 2);
    if (rem > 0) {
        qk_cos_tail<<<1, 32>>>(x, out, n4 << 2, n);
    }
}

// round 2
// speedup vs baseline: 1.3077x; 1.3077x over previous
#include <cuda_runtime.h>

// out[b][w] = cos(x[b][w])  (analytical collapse of the circuit; weights unused).
// R2: replace libm cosf (slow-path range reduction, ~30 instr, long dep chains)
// with MUFU-based __cosf; add ILP=2 float4 per thread to batch LDG.128s.

__global__ void __launch_bounds__(256) qk_cos2(const float4* __restrict__ x,
                                               float4* __restrict__ out, int n4) {
    int i = (blockIdx.x * blockDim.x + threadIdx.x) * 2;
    if (i + 1 < n4) {
        // front-batch both 128-bit loads (MLP=2)
        float4 v0 = x[i];
        float4 v1 = x[i + 1];
        float4 r0, r1;
        r0.x = __cosf(v0.x); r0.y = __cosf(v0.y);
        r0.z = __cosf(v0.z); r0.w = __cosf(v0.w);
        r1.x = __cosf(v1.x); r1.y = __cosf(v1.y);
        r1.z = __cosf(v1.z); r1.w = __cosf(v1.w);
        out[i] = r0;
        out[i + 1] = r1;
    } else if (i < n4) {
        float4 v0 = x[i];
        float4 r0;
        r0.x = __cosf(v0.x); r0.y = __cosf(v0.y);
        r0.z = __cosf(v0.z); r0.w = __cosf(v0.w);
        out[i] = r0;
    }
}

__global__ void qk_cos_tail(const float* __restrict__ x, float* __restrict__ out,
                            int start, int n) {
    int i = start + blockIdx.x * blockDim.x + threadIdx.x;
    if (i < n) out[i] = __cosf(x[i]);
}

extern "C" void kernel_launch(void* const* d_in, const int* in_sizes, int n_in,
                              void* d_out, int out_size) {
    const float* x = (const float*)d_in[0];   // (262144, 4) float32
    float* out = (float*)d_out;
    int n = out_size;          // 1048576
    int n4 = n >> 2;           // 262144 float4s

    const int T = 256;
    int threads_needed = (n4 + 1) >> 1;           // 2 float4 per thread
    int blocks = (threads_needed + T - 1) / T;    // 512 for this shape
    qk_cos2<<<blocks, T>>>((const float4*)x, (float4*)out, n4);

    int rem = n - (n4 << 2);
    if (rem > 0) qk_cos_tail<<<1, 32>>>(x, out, n4 << 2, n);
}